// round 3
// baseline (speedup 1.0000x reference)
#include <cuda_runtime.h>

#define NN     8
#define CC     21
#define HWP    262144      // 512*512
#define NPAIR  (HWP / 2)   // 131072 pixel-pairs per sample
#define OLDCL  16
#define IGN    255
#define NCLS   6           // classes that can appear as labels: 0, 16..20
#define GX     111         // blocks per sample; 111*8 = 888 = 148 SMs * 6 blocks
#define TPB    256

// scratch: per-sample [T[0..5], H[0..5], vcount, pad...] -> 16 floats per sample.
// Zero-initialized at module load; the last block resets it after finalize so
// every graph replay starts from the same state.
__device__ float        g_part[NN * 16];
__device__ unsigned int g_done = 0;

__device__ __forceinline__ void pixel_acc(int tj, float s, float s16, float sel,
                                          float* accT, float* accH, float& vc) {
    float L21 = __logf(s);
    int idx = (tj < OLDCL) ? 0 : (tj - (OLDCL - 1));   // 0, or 1..5 for classes 16..20
    float lp  = (idx == 0) ? (__logf(s16) - L21) : (sel - L21);
    bool valid = (tj != IGN);
#pragma unroll
    for (int k = 0; k < NCLS; k++) {
        bool m = valid && (idx == k);
        if (m) { accT[k] += lp; accH[k] += 1.0f; }
    }
    vc += valid ? 1.0f : 0.0f;
}

__global__ __launch_bounds__(TPB, 6) void fused_k(const float* __restrict__ in,
                                                  const int* __restrict__ tg,
                                                  float* __restrict__ out) {
    int n = blockIdx.y;
    const float* base = in + (size_t)n * CC * HWP;
    const int*   t    = tg + (size_t)n * HWP;

    float accT[NCLS] = {0, 0, 0, 0, 0, 0};
    float accH[NCLS] = {0, 0, 0, 0, 0, 0};
    float vc = 0.0f;

    const int stride = GX * TPB;                    // 28416 threads per sample
    for (int g = blockIdx.x * TPB + threadIdx.x; g < NPAIR; g += stride) {
        int p = g * 2;
        int2 tv = *reinterpret_cast<const int2*>(t + p);

        float2 s   = make_float2(0.f, 0.f);
        float2 s16 = make_float2(0.f, 0.f);
        float2 sel = make_float2(0.f, 0.f);
#pragma unroll
        for (int c = 0; c < CC; c++) {
            float2 xv = *reinterpret_cast<const float2*>(base + (size_t)c * HWP + p);
            s.x += __expf(xv.x);
            s.y += __expf(xv.y);
            if (c == OLDCL - 1) s16 = s;            // sum over channels 0..15
            sel.x = (c == tv.x) ? xv.x : sel.x;
            sel.y = (c == tv.y) ? xv.y : sel.y;
        }
        pixel_acc(tv.x, s.x, s16.x, sel.x, accT, accH, vc);
        pixel_acc(tv.y, s.y, s16.y, sel.y, accT, accH, vc);
    }

    // ---- block reduction of 13 values (6 T + 6 H + vcount) ----
    float vals[13];
#pragma unroll
    for (int k = 0; k < NCLS; k++) { vals[k] = accT[k]; vals[k + NCLS] = accH[k]; }
    vals[12] = vc;

    __shared__ float sh[8][13];
    int lane = threadIdx.x & 31;
    int wid  = threadIdx.x >> 5;
#pragma unroll
    for (int k = 0; k < 13; k++) {
        float v = vals[k];
        v += __shfl_down_sync(0xffffffffu, v, 16);
        v += __shfl_down_sync(0xffffffffu, v, 8);
        v += __shfl_down_sync(0xffffffffu, v, 4);
        v += __shfl_down_sync(0xffffffffu, v, 2);
        v += __shfl_down_sync(0xffffffffu, v, 1);
        if (lane == 0) sh[wid][k] = v;
    }
    __syncthreads();
    if (wid == 0) {
#pragma unroll
        for (int k = 0; k < 13; k++) {
            float v = (lane < 8) ? sh[lane][k] : 0.0f;
            v += __shfl_down_sync(0xffffffffu, v, 4);
            v += __shfl_down_sync(0xffffffffu, v, 2);
            v += __shfl_down_sync(0xffffffffu, v, 1);
            if (lane == 0) atomicAdd(&g_part[n * 16 + k], v);
        }
    }

    // ---- last-block finalize (threadfence reduction pattern) ----
    __shared__ int is_last;
    __threadfence();                                 // publish g_part atomics
    if (threadIdx.x == 0) {
        unsigned int v = atomicAdd(&g_done, 1u);
        is_last = (v == (unsigned)(GX * NN) - 1u) ? 1 : 0;
    }
    __syncthreads();
    if (!is_last) return;

    __threadfence();                                 // acquire all producers' writes
    if (wid == 0) {
        float num = 0.0f, den = 0.0f;
        if (lane < NN) {
            float T[NCLS], H[NCLS];
#pragma unroll
            for (int k = 0; k < NCLS; k++) {
                T[k] = __ldcg(&g_part[lane * 16 + k]);
                H[k] = __ldcg(&g_part[lane * 16 + NCLS + k]);
            }
            float vcn = __ldcg(&g_part[lane * 16 + 12]);
            float hs[NCLS], S = 0.0f;
#pragma unroll
            for (int k = 0; k < NCLS; k++) {
                hs[k] = (H[k] == 0.0f) ? 1.0f : H[k];   // empty classes -> 1 (RATIO=1)
                S += hs[k];
            }
            float c = 0.0f;
#pragma unroll
            for (int k = 0; k < NCLS; k++) c += (S / hs[k]) * T[k];  // weight = S/h
            num = c;
            den = vcn;
        }
        num += __shfl_down_sync(0xffffffffu, num, 4);
        den += __shfl_down_sync(0xffffffffu, den, 4);
        num += __shfl_down_sync(0xffffffffu, num, 2);
        den += __shfl_down_sync(0xffffffffu, den, 2);
        num += __shfl_down_sync(0xffffffffu, num, 1);
        den += __shfl_down_sync(0xffffffffu, den, 1);
        if (lane == 0) out[0] = -num / den;
    }
    __syncthreads();                                 // finalize reads done before reset
    // reset scratch so the next graph replay starts from zero state
    if (threadIdx.x < NN * 16) g_part[threadIdx.x] = 0.0f;
    if (threadIdx.x == 0)      g_done = 0;
}

extern "C" void kernel_launch(void* const* d_in, const int* in_sizes, int n_in,
                              void* d_out, int out_size) {
    const float* in;
    const int*   tg;
    // inputs tensor is the big one (N*C*H*W); targets is N*H*W
    if (in_sizes[0] > in_sizes[1]) {
        in = (const float*)d_in[0];
        tg = (const int*)d_in[1];
    } else {
        in = (const float*)d_in[1];
        tg = (const int*)d_in[0];
    }
    dim3 grid(GX, NN);
    fused_k<<<grid, TPB>>>(in, tg, (float*)d_out);
}

// round 4
// speedup vs baseline: 1.1565x; 1.1565x over previous
#include <cuda_runtime.h>

#define NN     8
#define CC     21
#define HWP    262144      // 512*512
#define OLDCL  16
#define IGN    255
#define NCLS   6           // classes that can appear as labels: 0, 16..20
#define GX     74          // 74*8 = 592 blocks = 148 SMs * 4
#define TPB    256

// scratch: per-sample [T[0..5], H[0..5], vcount, pad...] -> 16 floats per sample.
// Zero-initialized at module load; the last block resets it after finalize so
// every graph replay starts from the same state.
__device__ float        g_part[NN * 16];
__device__ unsigned int g_done = 0;

__device__ __forceinline__ void pixel_acc(int tj, float s, float s16, float sel,
                                          float* accT, float* accH, float& vc) {
    float L21 = __logf(s);
    int idx = (tj < OLDCL) ? 0 : (tj - (OLDCL - 1));   // 0, or 1..5 for classes 16..20
    float lp  = (idx == 0) ? (__logf(s16) - L21) : (sel - L21);
    bool valid = (tj != IGN);
#pragma unroll
    for (int k = 0; k < NCLS; k++) {
        bool m = valid && (idx == k);
        if (m) { accT[k] += lp; accH[k] += 1.0f; }
    }
    vc += valid ? 1.0f : 0.0f;
}

__global__ __launch_bounds__(TPB) void fused_k(const float* __restrict__ in,
                                               const int* __restrict__ tg,
                                               float* __restrict__ out) {
    int n = blockIdx.y;
    const float* base = in + (size_t)n * CC * HWP;
    const int*   t    = tg + (size_t)n * HWP;

    float accT[NCLS] = {0, 0, 0, 0, 0, 0};
    float accH[NCLS] = {0, 0, 0, 0, 0, 0};
    float vc = 0.0f;

    const int stride = GX * TPB;                       // 18944 threads per sample
    for (int g = blockIdx.x * TPB + threadIdx.x; g < HWP / 4; g += stride) {
        int p = g * 4;
        int4 tv = *reinterpret_cast<const int4*>(t + p);

        float4 s   = make_float4(0.f, 0.f, 0.f, 0.f);
        float4 s16 = make_float4(0.f, 0.f, 0.f, 0.f);
        float4 sel = make_float4(0.f, 0.f, 0.f, 0.f);

        // 21 channels = 3 batches of 7: loads hoisted into a register batch
        // BEFORE any exp consumes them -> 7 LDG.128 in flight per warp.
#pragma unroll
        for (int b = 0; b < 3; b++) {
            float4 xv[7];
#pragma unroll
            for (int j = 0; j < 7; j++) {
                int c = b * 7 + j;
                xv[j] = __ldcs(reinterpret_cast<const float4*>(base + (size_t)c * HWP + p));
            }
#pragma unroll
            for (int j = 0; j < 7; j++) {
                int c = b * 7 + j;
                s.x += __expf(xv[j].x);
                s.y += __expf(xv[j].y);
                s.z += __expf(xv[j].z);
                s.w += __expf(xv[j].w);
                if (c == OLDCL - 1) s16 = s;           // sum over channels 0..15
                if (c >= OLDCL) {                      // only channels 16..20 can be picked
                    sel.x = (c == tv.x) ? xv[j].x : sel.x;
                    sel.y = (c == tv.y) ? xv[j].y : sel.y;
                    sel.z = (c == tv.z) ? xv[j].z : sel.z;
                    sel.w = (c == tv.w) ? xv[j].w : sel.w;
                }
            }
        }
        pixel_acc(tv.x, s.x, s16.x, sel.x, accT, accH, vc);
        pixel_acc(tv.y, s.y, s16.y, sel.y, accT, accH, vc);
        pixel_acc(tv.z, s.z, s16.z, sel.z, accT, accH, vc);
        pixel_acc(tv.w, s.w, s16.w, sel.w, accT, accH, vc);
    }

    // ---- block reduction of 13 values (6 T + 6 H + vcount) ----
    float vals[13];
#pragma unroll
    for (int k = 0; k < NCLS; k++) { vals[k] = accT[k]; vals[k + NCLS] = accH[k]; }
    vals[12] = vc;

    __shared__ float sh[8][13];
    int lane = threadIdx.x & 31;
    int wid  = threadIdx.x >> 5;
#pragma unroll
    for (int k = 0; k < 13; k++) {
        float v = vals[k];
        v += __shfl_down_sync(0xffffffffu, v, 16);
        v += __shfl_down_sync(0xffffffffu, v, 8);
        v += __shfl_down_sync(0xffffffffu, v, 4);
        v += __shfl_down_sync(0xffffffffu, v, 2);
        v += __shfl_down_sync(0xffffffffu, v, 1);
        if (lane == 0) sh[wid][k] = v;
    }
    __syncthreads();
    if (wid == 0) {
#pragma unroll
        for (int k = 0; k < 13; k++) {
            float v = (lane < 8) ? sh[lane][k] : 0.0f;
            v += __shfl_down_sync(0xffffffffu, v, 4);
            v += __shfl_down_sync(0xffffffffu, v, 2);
            v += __shfl_down_sync(0xffffffffu, v, 1);
            if (lane == 0) atomicAdd(&g_part[n * 16 + k], v);
        }
    }

    // ---- last-block finalize (threadfence reduction pattern) ----
    __shared__ int is_last;
    __threadfence();                                 // publish g_part atomics
    if (threadIdx.x == 0) {
        unsigned int v = atomicAdd(&g_done, 1u);
        is_last = (v == (unsigned)(GX * NN) - 1u) ? 1 : 0;
    }
    __syncthreads();
    if (!is_last) return;

    __threadfence();                                 // acquire all producers' writes
    if (wid == 0) {
        float num = 0.0f, den = 0.0f;
        if (lane < NN) {
            float T[NCLS], H[NCLS];
#pragma unroll
            for (int k = 0; k < NCLS; k++) {
                T[k] = __ldcg(&g_part[lane * 16 + k]);
                H[k] = __ldcg(&g_part[lane * 16 + NCLS + k]);
            }
            float vcn = __ldcg(&g_part[lane * 16 + 12]);
            float hs[NCLS], S = 0.0f;
#pragma unroll
            for (int k = 0; k < NCLS; k++) {
                hs[k] = (H[k] == 0.0f) ? 1.0f : H[k];   // empty classes -> 1 (RATIO=1)
                S += hs[k];
            }
            float c = 0.0f;
#pragma unroll
            for (int k = 0; k < NCLS; k++) c += (S / hs[k]) * T[k];  // weight = S/h
            num = c;
            den = vcn;
        }
        num += __shfl_down_sync(0xffffffffu, num, 4);
        den += __shfl_down_sync(0xffffffffu, den, 4);
        num += __shfl_down_sync(0xffffffffu, num, 2);
        den += __shfl_down_sync(0xffffffffu, den, 2);
        num += __shfl_down_sync(0xffffffffu, num, 1);
        den += __shfl_down_sync(0xffffffffu, den, 1);
        if (lane == 0) out[0] = -num / den;
    }
    __syncthreads();                                 // finalize reads done before reset
    // reset scratch so the next graph replay starts from zero state
    if (threadIdx.x < NN * 16) g_part[threadIdx.x] = 0.0f;
    if (threadIdx.x == 0)      g_done = 0;
}

extern "C" void kernel_launch(void* const* d_in, const int* in_sizes, int n_in,
                              void* d_out, int out_size) {
    const float* in;
    const int*   tg;
    // inputs tensor is the big one (N*C*H*W); targets is N*H*W
    if (in_sizes[0] > in_sizes[1]) {
        in = (const float*)d_in[0];
        tg = (const int*)d_in[1];
    } else {
        in = (const float*)d_in[1];
        tg = (const int*)d_in[0];
    }
    dim3 grid(GX, NN);
    fused_k<<<grid, TPB>>>(in, tg, (float*)d_out);
}

// round 5
// speedup vs baseline: 1.1574x; 1.0009x over previous
#include <cuda_runtime.h>

#define NN     8
#define CC     21
#define HWP    262144      // 512*512
#define NQUAD  (HWP / 4)   // 65536 pixel-quads per sample
#define OLDCL  16
#define IGN    255
#define NCLS   6           // classes that can appear as labels: 0, 16..20
#define GX     56          // 56*8 = 448 blocks ~ 148 SMs * 3 resident
#define TPB    256

// scratch: per-sample [T[0..5], H[0..5], vcount, pad...] -> 16 floats per sample.
// Zero-initialized at module load; the last block resets it after finalize so
// every graph replay starts from the same state.
__device__ float        g_part[NN * 16];
__device__ unsigned int g_done = 0;

__device__ __forceinline__ void pixel_acc(int tj, float s, float s16, float sel,
                                          float* accT, float* accH, float& vc) {
    float L21 = __logf(s);
    int idx = (tj < OLDCL) ? 0 : (tj - (OLDCL - 1));   // 0, or 1..5 for classes 16..20
    float lp  = (idx == 0) ? (__logf(s16) - L21) : (sel - L21);
    bool valid = (tj != IGN);
#pragma unroll
    for (int k = 0; k < NCLS; k++) {
        bool m = valid && (idx == k);
        if (m) { accT[k] += lp; accH[k] += 1.0f; }
    }
    vc += valid ? 1.0f : 0.0f;
}

__global__ __launch_bounds__(TPB, 3) void fused_k(const float* __restrict__ in,
                                                  const int* __restrict__ tg,
                                                  float* __restrict__ out) {
    int n = blockIdx.y;
    const float* base = in + (size_t)n * CC * HWP;
    const int*   t    = tg + (size_t)n * HWP;

    float accT[NCLS] = {0, 0, 0, 0, 0, 0};
    float accH[NCLS] = {0, 0, 0, 0, 0, 0};
    float vc = 0.0f;

    const int stride = GX * TPB;                       // 14336 threads per sample
    for (int g = blockIdx.x * TPB + threadIdx.x; g < NQUAD; g += stride) {
        int p = g * 4;
        int4 tv = *reinterpret_cast<const int4*>(t + p);

        float4 s = make_float4(0.f, 0.f, 0.f, 0.f);
        float4 s16, sel = make_float4(0.f, 0.f, 0.f, 0.f);

        // Software pipeline over channel batches [4,4,4,4,5]:
        // while consuming batch b, batch b+1's loads are already in flight.
        float4 buf[5], nbuf[5];
#pragma unroll
        for (int j = 0; j < 4; j++)         // prime: batch 0 = channels 0..3
            buf[j] = __ldcs(reinterpret_cast<const float4*>(base + (size_t)j * HWP + p));

#pragma unroll
        for (int b = 0; b < 4; b++) {
            int cn = (b + 1) * 4;           // next batch start channel
            int nsz = (b == 3) ? 5 : 4;     // last batch has 5 channels (16..20)
#pragma unroll
            for (int j = 0; j < 5; j++)
                if (j < nsz)
                    nbuf[j] = __ldcs(reinterpret_cast<const float4*>(
                        base + (size_t)(cn + j) * HWP + p));
            // consume batch b (channels 4b .. 4b+3) — pure exp accumulation
#pragma unroll
            for (int j = 0; j < 4; j++) {
                s.x += __expf(buf[j].x);
                s.y += __expf(buf[j].y);
                s.z += __expf(buf[j].z);
                s.w += __expf(buf[j].w);
            }
#pragma unroll
            for (int j = 0; j < 5; j++) buf[j] = nbuf[j];
        }
        s16 = s;                            // after channels 0..15
        // consume final batch: channels 16..20, with label-select tracking
#pragma unroll
        for (int j = 0; j < 5; j++) {
            int c = OLDCL + j;
            s.x += __expf(buf[j].x);
            s.y += __expf(buf[j].y);
            s.z += __expf(buf[j].z);
            s.w += __expf(buf[j].w);
            sel.x = (c == tv.x) ? buf[j].x : sel.x;
            sel.y = (c == tv.y) ? buf[j].y : sel.y;
            sel.z = (c == tv.z) ? buf[j].z : sel.z;
            sel.w = (c == tv.w) ? buf[j].w : sel.w;
        }

        pixel_acc(tv.x, s.x, s16.x, sel.x, accT, accH, vc);
        pixel_acc(tv.y, s.y, s16.y, sel.y, accT, accH, vc);
        pixel_acc(tv.z, s.z, s16.z, sel.z, accT, accH, vc);
        pixel_acc(tv.w, s.w, s16.w, sel.w, accT, accH, vc);
    }

    // ---- block reduction of 13 values (6 T + 6 H + vcount) ----
    float vals[13];
#pragma unroll
    for (int k = 0; k < NCLS; k++) { vals[k] = accT[k]; vals[k + NCLS] = accH[k]; }
    vals[12] = vc;

    __shared__ float sh[8][13];
    int lane = threadIdx.x & 31;
    int wid  = threadIdx.x >> 5;
#pragma unroll
    for (int k = 0; k < 13; k++) {
        float v = vals[k];
        v += __shfl_down_sync(0xffffffffu, v, 16);
        v += __shfl_down_sync(0xffffffffu, v, 8);
        v += __shfl_down_sync(0xffffffffu, v, 4);
        v += __shfl_down_sync(0xffffffffu, v, 2);
        v += __shfl_down_sync(0xffffffffu, v, 1);
        if (lane == 0) sh[wid][k] = v;
    }
    __syncthreads();
    if (wid == 0) {
#pragma unroll
        for (int k = 0; k < 13; k++) {
            float v = (lane < 8) ? sh[lane][k] : 0.0f;
            v += __shfl_down_sync(0xffffffffu, v, 4);
            v += __shfl_down_sync(0xffffffffu, v, 2);
            v += __shfl_down_sync(0xffffffffu, v, 1);
            if (lane == 0) atomicAdd(&g_part[n * 16 + k], v);
        }
    }

    // ---- last-block finalize (threadfence reduction pattern) ----
    __shared__ int is_last;
    __threadfence();                                 // publish g_part atomics
    if (threadIdx.x == 0) {
        unsigned int v = atomicAdd(&g_done, 1u);
        is_last = (v == (unsigned)(GX * NN) - 1u) ? 1 : 0;
    }
    __syncthreads();
    if (!is_last) return;

    __threadfence();                                 // acquire all producers' writes
    if (wid == 0) {
        float num = 0.0f, den = 0.0f;
        if (lane < NN) {
            float T[NCLS], H[NCLS];
#pragma unroll
            for (int k = 0; k < NCLS; k++) {
                T[k] = __ldcg(&g_part[lane * 16 + k]);
                H[k] = __ldcg(&g_part[lane * 16 + NCLS + k]);
            }
            float vcn = __ldcg(&g_part[lane * 16 + 12]);
            float hs[NCLS], S = 0.0f;
#pragma unroll
            for (int k = 0; k < NCLS; k++) {
                hs[k] = (H[k] == 0.0f) ? 1.0f : H[k];   // empty classes -> 1 (RATIO=1)
                S += hs[k];
            }
            float c = 0.0f;
#pragma unroll
            for (int k = 0; k < NCLS; k++) c += (S / hs[k]) * T[k];  // weight = S/h
            num = c;
            den = vcn;
        }
        num += __shfl_down_sync(0xffffffffu, num, 4);
        den += __shfl_down_sync(0xffffffffu, den, 4);
        num += __shfl_down_sync(0xffffffffu, num, 2);
        den += __shfl_down_sync(0xffffffffu, den, 2);
        num += __shfl_down_sync(0xffffffffu, num, 1);
        den += __shfl_down_sync(0xffffffffu, den, 1);
        if (lane == 0) out[0] = -num / den;
    }
    __syncthreads();                                 // finalize reads done before reset
    // reset scratch so the next graph replay starts from zero state
    if (threadIdx.x < NN * 16) g_part[threadIdx.x] = 0.0f;
    if (threadIdx.x == 0)      g_done = 0;
}

extern "C" void kernel_launch(void* const* d_in, const int* in_sizes, int n_in,
                              void* d_out, int out_size) {
    const float* in;
    const int*   tg;
    // inputs tensor is the big one (N*C*H*W); targets is N*H*W
    if (in_sizes[0] > in_sizes[1]) {
        in = (const float*)d_in[0];
        tg = (const int*)d_in[1];
    } else {
        in = (const float*)d_in[1];
        tg = (const int*)d_in[0];
    }
    dim3 grid(GX, NN);
    fused_k<<<grid, TPB>>>(in, tg, (float*)d_out);
}